// round 8
// baseline (speedup 1.0000x reference)
#include <cuda_runtime.h>
#include <cuda_bf16.h>
#include <cstdint>

// Inputs (metadata order):
//   d_in[0] features  : float32 [100000*128]
//   d_in[1] neigh_ids : int32   [1600000]
//   d_in[2] row_ids   : int32   [1600000]   (SORTED ascending, ~uniform)
//   d_in[3] num_segments (scalar, ignored; derived from out_size)
// Output: float32 [num_rows * 128]

#define D_FEAT 128
#define MAX_ROWS 50008

__device__ int g_offsets[MAX_ROWS + 1];

// Kernel 1: g_offsets[r] = lower_bound(row_ids, E, r); g_offsets[R] = E
// row_ids sorted ~uniform -> lower_bound(r) ~= r*E/R +- ~700 (binomial std).
// Probe a +/-8K window (2 validation loads), fall back to full range.
__global__ void compute_offsets_kernel(const int* __restrict__ row_ids,
                                       int E, int R) {
    int r = blockIdx.x * blockDim.x + threadIdx.x;
    if (r > R) return;
    if (r == R) { g_offsets[R] = E; return; }

    const int W = 8192;
    int est = (int)(((long long)r * (long long)E) / (long long)R);
    int wlo = est - W; if (wlo < 0) wlo = 0;
    int whi = est + W; if (whi > E) whi = E;

    bool below_ok = (wlo == 0) || (__ldg(&row_ids[wlo - 1]) < r);
    bool above_ok = (whi == E) || (__ldg(&row_ids[whi]) >= r);

    int lo, hi;
    if (below_ok && above_ok) { lo = wlo; hi = whi; }
    else                      { lo = 0;   hi = E;   }

    while (lo < hi) {
        int mid = (lo + hi) >> 1;
        if (__ldg(&row_ids[mid]) < r) lo = mid + 1;
        else                          hi = mid;
    }
    g_offsets[r] = lo;
}

// Kernel 2: one warp per output row; lane = 4 features (float4).
// Ids are fetched 32-at-a-time with ONE coalesced LDG per chunk and
// broadcast via shfl (no per-edge broadcast loads). Gathers are issued
// 8-wide for MLP. Output uses streaming stores to preserve L1 for the
// feature table.
__global__ void __launch_bounds__(64)
mean_agg_kernel(const float* __restrict__ features,
                const int* __restrict__ neigh_ids,
                float* __restrict__ out, int R) {
    const int warp_id = threadIdx.x >> 5;
    const int lane    = threadIdx.x & 31;
    const int row     = blockIdx.x * 2 + warp_id;
    if (row >= R) return;

    const int start = g_offsets[row];
    const int end   = g_offsets[row + 1];

    const float4* __restrict__ feat4 = (const float4*)features;

    float4 acc = make_float4(0.f, 0.f, 0.f, 0.f);

    int e = start;
    while (e < end) {
        const int chunk = min(32, end - e);
        // one coalesced id load for up to 32 edges
        int myid = 0;
        if (lane < chunk) myid = __ldg(&neigh_ids[e + lane]);

        int j = 0;
        for (; j + 8 <= chunk; j += 8) {
            int n0 = __shfl_sync(0xffffffffu, myid, j + 0);
            int n1 = __shfl_sync(0xffffffffu, myid, j + 1);
            int n2 = __shfl_sync(0xffffffffu, myid, j + 2);
            int n3 = __shfl_sync(0xffffffffu, myid, j + 3);
            int n4 = __shfl_sync(0xffffffffu, myid, j + 4);
            int n5 = __shfl_sync(0xffffffffu, myid, j + 5);
            int n6 = __shfl_sync(0xffffffffu, myid, j + 6);
            int n7 = __shfl_sync(0xffffffffu, myid, j + 7);
            float4 v0 = __ldg(&feat4[(size_t)n0 * 32 + lane]);
            float4 v1 = __ldg(&feat4[(size_t)n1 * 32 + lane]);
            float4 v2 = __ldg(&feat4[(size_t)n2 * 32 + lane]);
            float4 v3 = __ldg(&feat4[(size_t)n3 * 32 + lane]);
            float4 v4 = __ldg(&feat4[(size_t)n4 * 32 + lane]);
            float4 v5 = __ldg(&feat4[(size_t)n5 * 32 + lane]);
            float4 v6 = __ldg(&feat4[(size_t)n6 * 32 + lane]);
            float4 v7 = __ldg(&feat4[(size_t)n7 * 32 + lane]);
            // pairwise add tree
            v0.x += v1.x; v0.y += v1.y; v0.z += v1.z; v0.w += v1.w;
            v2.x += v3.x; v2.y += v3.y; v2.z += v3.z; v2.w += v3.w;
            v4.x += v5.x; v4.y += v5.y; v4.z += v5.z; v4.w += v5.w;
            v6.x += v7.x; v6.y += v7.y; v6.z += v7.z; v6.w += v7.w;
            v0.x += v2.x; v0.y += v2.y; v0.z += v2.z; v0.w += v2.w;
            v4.x += v6.x; v4.y += v6.y; v4.z += v6.z; v4.w += v6.w;
            acc.x += v0.x + v4.x;
            acc.y += v0.y + v4.y;
            acc.z += v0.z + v4.z;
            acc.w += v0.w + v4.w;
        }
        for (; j < chunk; ++j) {
            int n = __shfl_sync(0xffffffffu, myid, j);
            float4 v = __ldg(&feat4[(size_t)n * 32 + lane]);
            acc.x += v.x; acc.y += v.y; acc.z += v.z; acc.w += v.w;
        }
        e += chunk;
    }

    float cnt = (float)(end - start);
    float inv = 1.0f / fmaxf(cnt, 1.0f);
    acc.x *= inv; acc.y *= inv; acc.z *= inv; acc.w *= inv;

    // streaming store: don't pollute L1 with output lines
    float4* out4 = (float4*)out;
    __stcs(&out4[(size_t)row * 32 + lane], acc);
}

extern "C" void kernel_launch(void* const* d_in, const int* in_sizes, int n_in,
                              void* d_out, int out_size) {
    const float* features  = (const float*)d_in[0];
    const int*   neigh_ids = (const int*)d_in[1];
    const int*   row_ids   = (const int*)d_in[2];
    float* out = (float*)d_out;

    const int E = in_sizes[1];
    const int R = out_size / D_FEAT;

    {
        int threads = 256;
        int blocks  = (R + 1 + threads - 1) / threads;
        compute_offsets_kernel<<<blocks, threads>>>(row_ids, E, R);
    }
    {
        int threads = 64;                   // 2 warps = 2 rows per block
        int blocks  = (R + 1) / 2;
        mean_agg_kernel<<<blocks, threads>>>(features, neigh_ids, out, R);
    }
}

// round 12
// speedup vs baseline: 1.0679x; 1.0679x over previous
#include <cuda_runtime.h>
#include <cuda_bf16.h>
#include <cstdint>

// Inputs (metadata order):
//   d_in[0] features  : float32 [100000*128]
//   d_in[1] neigh_ids : int32   [1600000]
//   d_in[2] row_ids   : int32   [1600000]   (SORTED ascending, ~uniform)
//   d_in[3] num_segments (scalar, ignored; derived from out_size)
// Output: float32 [num_rows * 128]

#define D_FEAT 128
#define MAX_ROWS 50008

__device__ int g_offsets[MAX_ROWS + 1];

// Kernel 1: g_offsets[r] = lower_bound(row_ids, E, r); g_offsets[R] = E
// row_ids sorted ~uniform -> lower_bound(r) ~= r*E/R. Windowed search.
__global__ void compute_offsets_kernel(const int* __restrict__ row_ids,
                                       int E, int R) {
    int r = blockIdx.x * blockDim.x + threadIdx.x;
    if (r > R) return;
    if (r == R) { g_offsets[R] = E; return; }

    const int W = 8192;
    int est = (int)(((long long)r * (long long)E) / (long long)R);
    int wlo = est - W; if (wlo < 0) wlo = 0;
    int whi = est + W; if (whi > E) whi = E;

    bool below_ok = (wlo == 0) || (__ldg(&row_ids[wlo - 1]) < r);
    bool above_ok = (whi == E) || (__ldg(&row_ids[whi]) >= r);

    int lo, hi;
    if (below_ok && above_ok) { lo = wlo; hi = whi; }
    else                      { lo = 0;   hi = E;   }

    while (lo < hi) {
        int mid = (lo + hi) >> 1;
        if (__ldg(&row_ids[mid]) < r) lo = mid + 1;
        else                          hi = mid;
    }
    g_offsets[r] = lo;
}

// Kernel 2: one warp per output row; lane = 2 features in each row half
// (float2 gathers -> each LDG.64 warp-request touches only 2 cache lines,
// avoiding the 4-line replay cost of LDG.128). 4-wide edge unroll = 8
// independent float2 gathers in flight.
__global__ void __launch_bounds__(64)
mean_agg_kernel(const float* __restrict__ features,
                const int* __restrict__ neigh_ids,
                float* __restrict__ out, int R) {
    const int warp_id = threadIdx.x >> 5;
    const int lane    = threadIdx.x & 31;
    const int row     = blockIdx.x * 2 + warp_id;
    if (row >= R) return;

    const int start = g_offsets[row];
    const int end   = g_offsets[row + 1];

    const float2* __restrict__ feat2 = (const float2*)features;  // row = 64 float2

    float2 acc_lo = make_float2(0.f, 0.f);   // feats [2*lane, 2*lane+1]
    float2 acc_hi = make_float2(0.f, 0.f);   // feats [64+2*lane, 64+2*lane+1]

    int e = start;
    // 4 edges per iteration: 4 id loads, then 8 independent float2 gathers
    for (; e + 4 <= end; e += 4) {
        int n0 = __ldg(&neigh_ids[e + 0]);
        int n1 = __ldg(&neigh_ids[e + 1]);
        int n2 = __ldg(&neigh_ids[e + 2]);
        int n3 = __ldg(&neigh_ids[e + 3]);
        const float2* p0 = &feat2[(size_t)n0 * 64 + lane];
        const float2* p1 = &feat2[(size_t)n1 * 64 + lane];
        const float2* p2 = &feat2[(size_t)n2 * 64 + lane];
        const float2* p3 = &feat2[(size_t)n3 * 64 + lane];
        float2 a0 = __ldg(p0);
        float2 a1 = __ldg(p1);
        float2 a2 = __ldg(p2);
        float2 a3 = __ldg(p3);
        float2 b0 = __ldg(p0 + 32);
        float2 b1 = __ldg(p1 + 32);
        float2 b2 = __ldg(p2 + 32);
        float2 b3 = __ldg(p3 + 32);
        a0.x += a1.x; a0.y += a1.y;
        a2.x += a3.x; a2.y += a3.y;
        b0.x += b1.x; b0.y += b1.y;
        b2.x += b3.x; b2.y += b3.y;
        acc_lo.x += a0.x + a2.x;  acc_lo.y += a0.y + a2.y;
        acc_hi.x += b0.x + b2.x;  acc_hi.y += b0.y + b2.y;
    }
    for (; e < end; ++e) {
        int n = __ldg(&neigh_ids[e]);
        const float2* p = &feat2[(size_t)n * 64 + lane];
        float2 a = __ldg(p);
        float2 b = __ldg(p + 32);
        acc_lo.x += a.x; acc_lo.y += a.y;
        acc_hi.x += b.x; acc_hi.y += b.y;
    }

    float cnt = (float)(end - start);
    float inv = 1.0f / fmaxf(cnt, 1.0f);
    acc_lo.x *= inv; acc_lo.y *= inv;
    acc_hi.x *= inv; acc_hi.y *= inv;

    // streaming stores: keep L1 for the feature table
    float2* out2 = (float2*)out;
    __stcs(&out2[(size_t)row * 64 + lane], acc_lo);
    __stcs(&out2[(size_t)row * 64 + 32 + lane], acc_hi);
}

extern "C" void kernel_launch(void* const* d_in, const int* in_sizes, int n_in,
                              void* d_out, int out_size) {
    const float* features  = (const float*)d_in[0];
    const int*   neigh_ids = (const int*)d_in[1];
    const int*   row_ids   = (const int*)d_in[2];
    float* out = (float*)d_out;

    const int E = in_sizes[1];
    const int R = out_size / D_FEAT;

    {
        int threads = 256;
        int blocks  = (R + 1 + threads - 1) / threads;
        compute_offsets_kernel<<<blocks, threads>>>(row_ids, E, R);
    }
    {
        int threads = 64;                   // 2 warps = 2 rows per block
        int blocks  = (R + 1) / 2;
        mean_agg_kernel<<<blocks, threads>>>(features, neigh_ids, out, R);
    }
}